// round 8
// baseline (speedup 1.0000x reference)
#include <cuda_runtime.h>
#include <cstdint>

// ---------------- problem constants ----------------
#define BB   2048      // batch
#define LL   64        // words / sentence
#define DD   300       // embedding dim (K of encoder GEMM)
#define CC   512       // conv out channels
#define HH   2048      // fc hidden
// encoder GEMM: M = BB*LL = 131072, N = CC = 512, K = 300 (padded 304)
// fc1 GEMM:     M = BB = 2048,     N = HH = 2048, K = 2*CC = 1024

// ---------------- scratch (no allocations allowed) ----------------
__device__ float g_e[2 * BB * CC];      // e1 | e2   (8 MB)
__device__ float g_h[(size_t)BB * HH];  // tanh hidden (16 MB)

// ---------------- helpers ----------------
__device__ __forceinline__ uint32_t f2tf(float f) {
    uint32_t r;
    asm("cvt.rna.tf32.f32 %0, %1;" : "=r"(r) : "f"(f));
    return r;
}

__device__ __forceinline__ void mma_tf32(float c[4], const uint32_t a[4], const uint32_t b[2]) {
    asm volatile(
        "mma.sync.aligned.m16n8k8.row.col.f32.tf32.tf32.f32 "
        "{%0,%1,%2,%3}, {%4,%5,%6,%7}, {%8,%9}, {%0,%1,%2,%3};"
        : "+f"(c[0]), "+f"(c[1]), "+f"(c[2]), "+f"(c[3])
        : "r"(a[0]), "r"(a[1]), "r"(a[2]), "r"(a[3]), "r"(b[0]), "r"(b[1]));
}

// ---------------- encode tiling ----------------
// CTA: 512 threads = 16 warps of 64(M)x32(N).  CTA tile 256 x 128.
// B (Wc block, 128 channels x 304 K) resident in smem for the whole CTA.
#define BPW   308                      // B slab row stride words (308%32=20: conflict-free)
#define APW   36                       // A stage row stride words (36%32=4: conflict-free)
#define AS_W  (256 * APW)              // words per A stage
#define ENC_SMEM ((128 * BPW + 2 * AS_W) * 4)   // 157696 + 73728 = 231424 B

// fc1: CTA 256 x 128, both operands streamed, double-buffered
#define BS_W  (128 * APW)
#define FC1_SMEM ((2 * (AS_W + BS_W)) * 4)      // 110592 B

// ---------------- per-warp compute (64x32 tile) ----------------
// A staged (stride APW), B with arbitrary stride/bias column kb.
template <int NKS>
__device__ __forceinline__ void wtile_compute(const uint32_t* __restrict__ As,
                                              const uint32_t* __restrict__ Bs,
                                              int bstride, int kb,
                                              int wm, int wn, int g, int tg,
                                              float acc[4][4][4])
{
    #pragma unroll
    for (int kk = 0; kk < NKS * 8; kk += 8) {
        uint32_t a[4][4], b[4][2];
        #pragma unroll
        for (int f = 0; f < 4; f++) {
            int r = wm * 64 + f * 16;
            a[f][0] = As[(r + g    ) * APW + kk + tg    ];
            a[f][1] = As[(r + g + 8) * APW + kk + tg    ];
            a[f][2] = As[(r + g    ) * APW + kk + tg + 4];
            a[f][3] = As[(r + g + 8) * APW + kk + tg + 4];
        }
        #pragma unroll
        for (int ni = 0; ni < 4; ni++) {
            int c = wn * 32 + ni * 8;
            b[ni][0] = Bs[(c + g) * bstride + kb + kk + tg    ];
            b[ni][1] = Bs[(c + g) * bstride + kb + kk + tg + 4];
        }
        #pragma unroll
        for (int f = 0; f < 4; f++)
            #pragma unroll
            for (int ni = 0; ni < 4; ni++)
                mma_tf32(acc[f][ni], a[f], b[ni]);
    }
}

// =====================================================================
// Kernel 1: encoder.  grid = (C/128, (B*L)/(256*4), 2), block = 512
// Wc block resident in smem; 4 M-tiles of 256 words per CTA.
// relu(max_L(.) + bc) folded into per-M-tile epilogue (warp m-strip = sentence).
// =====================================================================
__global__ __launch_bounds__(512, 1)
void encode_kernel(const float* __restrict__ x1, const float* __restrict__ x2,
                   const float* __restrict__ Wc, const float* __restrict__ bc)
{
    extern __shared__ uint32_t sh[];
    uint32_t* __restrict__ Bslab = sh;                 // 128 x BPW
    uint32_t* __restrict__ Ast   = sh + 128 * BPW;     // 2 x 256 x APW

    const int nb = blockIdx.x;                 // channel block (128 ch)
    const int cy = blockIdx.y;                 // M chunk (4 M-tiles of 256 words)
    const float* __restrict__ x = blockIdx.z ? x2 : x1;

    const int tid  = threadIdx.x;
    const int warp = tid >> 5, lane = tid & 31;
    const int wm = warp >> 2, wn = warp & 3;   // 4 x 4 warp grid
    const int g  = lane >> 2, tg = lane & 3;

    // ---- prologue: Wc block -> smem (tf32), zero-padded to 308 ----
    for (int t = tid; t < 128 * 77; t += 512) {
        int row = t / 77, ch = t % 77;         // 77 float4 chunks per row
        float4 v = make_float4(0.f, 0.f, 0.f, 0.f);
        if (ch < 75)
            v = *(const float4*)(Wc + (size_t)(nb * 128 + row) * DD + ch * 4);
        uint32_t* d = Bslab + row * BPW + ch * 4;
        d[0] = f2tf(v.x); d[1] = f2tf(v.y); d[2] = f2tf(v.z); d[3] = f2tf(v.w);
    }

    const int arow = tid >> 3;                 // + it*64
    const int kch  = (tid & 7) * 4;
    float4 ra[4];

    auto ldgA = [&](int mt, int kt) {
        const size_t mb = (size_t)(cy * 4 + mt) * 256;
        const int k = kt * 32 + kch;
        #pragma unroll
        for (int it = 0; it < 4; it++)
            ra[it] = (k < DD)
                ? *(const float4*)(x + (mb + arow + it * 64) * DD + k)
                : make_float4(0.f, 0.f, 0.f, 0.f);
    };
    auto stsA = [&](int p) {
        #pragma unroll
        for (int it = 0; it < 4; it++) {
            uint32_t* d = Ast + p * AS_W + (arow + it * 64) * APW + kch;
            d[0] = f2tf(ra[it].x); d[1] = f2tf(ra[it].y);
            d[2] = f2tf(ra[it].z); d[3] = f2tf(ra[it].w);
        }
    };

    float acc[4][4][4] = {};

    ldgA(0, 0);
    stsA(0);
    __syncthreads();      // also covers Bslab fill

    int p = 0;
    #pragma unroll 1
    for (int mt = 0; mt < 4; mt++) {
        #pragma unroll 1
        for (int kt = 0; kt < 10; kt++) {
            int nmt = mt, nkt = kt + 1;
            if (nkt == 10) { nkt = 0; nmt++; }
            const bool hn = (nmt < 4);
            if (hn) ldgA(nmt, nkt);

            if (kt == 9)
                wtile_compute<2>(Ast + p * AS_W, Bslab, BPW, 288, wm, wn, g, tg, acc);
            else
                wtile_compute<4>(Ast + p * AS_W, Bslab, BPW, kt * 32, wm, wn, g, tg, acc);

            if (hn) {
                stsA(p ^ 1);
                __syncthreads();
            }
            p ^= 1;
        }

        // ---- per-M-tile epilogue: max over 64 rows (one sentence) ----
        const int sent = (cy * 4 + mt) * 4 + wm;
        float* __restrict__ eo =
            g_e + ((size_t)blockIdx.z * BB + sent) * CC + nb * 128 + wn * 32;
        #pragma unroll
        for (int ni = 0; ni < 4; ni++) {
            #pragma unroll
            for (int j = 0; j < 2; j++) {
                float m = -3.4e38f;
                #pragma unroll
                for (int f = 0; f < 4; f++)
                    m = fmaxf(m, fmaxf(acc[f][ni][j], acc[f][ni][j + 2]));
                #pragma unroll
                for (int off = 4; off < 32; off <<= 1)
                    m = fmaxf(m, __shfl_xor_sync(0xffffffffu, m, off));
                if (g == 0) {
                    int col = ni * 8 + 2 * tg + j;
                    eo[col] = fmaxf(m + bc[nb * 128 + wn * 32 + col], 0.f);
                }
            }
        }
        #pragma unroll
        for (int f = 0; f < 4; f++)
            #pragma unroll
            for (int ni = 0; ni < 4; ni++)
                #pragma unroll
                for (int q = 0; q < 4; q++)
                    acc[f][ni][q] = 0.f;
    }
}

// =====================================================================
// Kernel 2: FC1.  grid = (H/128, B/256), block = 512
// feat = [e1-e2 | e1*e2] computed on the fly; h = tanh(feat @ W1^T + b1)
// =====================================================================
__global__ __launch_bounds__(512, 1)
void fc1_kernel(const float* __restrict__ W1, const float* __restrict__ b1)
{
    extern __shared__ uint32_t sh[];
    uint32_t* __restrict__ Ast = sh;                 // 2 x 256 x APW
    uint32_t* __restrict__ Bst = sh + 2 * AS_W;      // 2 x 128 x APW

    const int mbase = blockIdx.y * 256;
    const int nbase = blockIdx.x * 128;

    const int tid  = threadIdx.x;
    const int warp = tid >> 5, lane = tid & 31;
    const int wm = warp >> 2, wn = warp & 3;
    const int g  = lane >> 2, tg = lane & 3;

    const float* __restrict__ e1 = g_e;
    const float* __restrict__ e2 = g_e + (size_t)BB * CC;

    const int arow = tid >> 3;
    const int kch  = (tid & 7) * 4;

    float4 ra[4], rb[2];

    auto ldg = [&](int kb) {
        const int j = kb + kch;
        #pragma unroll
        for (int it = 0; it < 4; it++) {
            int r = mbase + arow + it * 64;
            if (j < CC) {
                float4 pv = *(const float4*)(e1 + (size_t)r * CC + j);
                float4 qv = *(const float4*)(e2 + (size_t)r * CC + j);
                ra[it] = make_float4(pv.x - qv.x, pv.y - qv.y, pv.z - qv.z, pv.w - qv.w);
            } else {
                int j2 = j - CC;
                float4 pv = *(const float4*)(e1 + (size_t)r * CC + j2);
                float4 qv = *(const float4*)(e2 + (size_t)r * CC + j2);
                ra[it] = make_float4(pv.x * qv.x, pv.y * qv.y, pv.z * qv.z, pv.w * qv.w);
            }
        }
        #pragma unroll
        for (int it = 0; it < 2; it++)
            rb[it] = *(const float4*)(W1 + (size_t)(nbase + arow + it * 64) * (2 * CC) + j);
    };
    auto sts = [&](int p) {
        #pragma unroll
        for (int it = 0; it < 4; it++) {
            uint32_t* d = Ast + p * AS_W + (arow + it * 64) * APW + kch;
            d[0] = f2tf(ra[it].x); d[1] = f2tf(ra[it].y);
            d[2] = f2tf(ra[it].z); d[3] = f2tf(ra[it].w);
        }
        #pragma unroll
        for (int it = 0; it < 2; it++) {
            uint32_t* d = Bst + p * BS_W + (arow + it * 64) * APW + kch;
            d[0] = f2tf(rb[it].x); d[1] = f2tf(rb[it].y);
            d[2] = f2tf(rb[it].z); d[3] = f2tf(rb[it].w);
        }
    };

    float acc[4][4][4] = {};

    ldg(0);
    sts(0);
    __syncthreads();

    const int NK = (2 * CC) / 32;   // 32
    int p = 0;
    #pragma unroll 1
    for (int i = 0; i < NK; i++) {
        const bool hn = (i + 1 < NK);
        if (hn) ldg((i + 1) * 32);

        wtile_compute<4>(Ast + p * AS_W, Bst + p * BS_W, APW, 0, wm, wn, g, tg, acc);

        if (hn) {
            sts(p ^ 1);
            __syncthreads();
        }
        p ^= 1;
    }

    // epilogue: bias + tanh, direct store
    #pragma unroll
    for (int f = 0; f < 4; f++) {
        #pragma unroll
        for (int ni = 0; ni < 4; ni++) {
            #pragma unroll
            for (int q = 0; q < 4; q++) {
                int row = mbase + wm * 64 + f * 16 + g + ((q >> 1) ? 8 : 0);
                int col = nbase + wn * 32 + ni * 8 + 2 * tg + (q & 1);
                g_h[(size_t)row * HH + col] = tanhf(acc[f][ni][q] + b1[col]);
            }
        }
    }
}

// =====================================================================
// Kernel 3: FC2 (H -> 1), fp32, float4 loads.  grid = B, block = 256
// =====================================================================
__global__ __launch_bounds__(256)
void fc2_kernel(const float* __restrict__ W2, const float* __restrict__ b2,
                float* __restrict__ out)
{
    const int b = blockIdx.x;
    const float4* __restrict__ h4 = (const float4*)(g_h + (size_t)b * HH);
    const float4* __restrict__ w4 = (const float4*)W2;
    float s = 0.f;
    #pragma unroll
    for (int i = 0; i < 2; i++) {
        int idx = threadIdx.x + i * 256;
        float4 hv = h4[idx], wv = w4[idx];
        s += hv.x * wv.x + hv.y * wv.y + hv.z * wv.z + hv.w * wv.w;
    }
    #pragma unroll
    for (int off = 16; off > 0; off >>= 1)
        s += __shfl_xor_sync(0xffffffffu, s, off);
    __shared__ float sm[8];
    int warp = threadIdx.x >> 5, lane = threadIdx.x & 31;
    if (lane == 0) sm[warp] = s;
    __syncthreads();
    if (warp == 0) {
        float v = (lane < 8) ? sm[lane] : 0.f;
        #pragma unroll
        for (int off = 4; off > 0; off >>= 1)
            v += __shfl_xor_sync(0xffffffffu, v, off);
        if (lane == 0) out[b] = v + b2[0];
    }
}

// =====================================================================
extern "C" void kernel_launch(void* const* d_in, const int* in_sizes, int n_in,
                              void* d_out, int out_size)
{
    (void)in_sizes; (void)n_in; (void)out_size;
    const float* x1 = (const float*)d_in[0];
    const float* x2 = (const float*)d_in[1];
    const float* Wc = (const float*)d_in[2];
    const float* bc = (const float*)d_in[3];
    const float* W1 = (const float*)d_in[4];
    const float* b1 = (const float*)d_in[5];
    const float* W2 = (const float*)d_in[6];
    const float* b2 = (const float*)d_in[7];
    float* out = (float*)d_out;

    static bool attr_done = false;
    if (!attr_done) {
        cudaFuncSetAttribute(encode_kernel,
                             cudaFuncAttributeMaxDynamicSharedMemorySize, ENC_SMEM);
        cudaFuncSetAttribute(fc1_kernel,
                             cudaFuncAttributeMaxDynamicSharedMemorySize, FC1_SMEM);
        attr_done = true;
    }

    dim3 g1(CC / 128, (BB * LL) / (256 * 4), 2);   // 4 x 128 x 2 = 1024 CTAs
    encode_kernel<<<g1, 512, ENC_SMEM>>>(x1, x2, Wc, bc);

    dim3 g2(HH / 128, BB / 256);                   // 16 x 8 = 128 CTAs
    fc1_kernel<<<g2, 512, FC1_SMEM>>>(W1, b1);

    fc2_kernel<<<BB, 256>>>(W2, b2, out);
}

// round 9
// speedup vs baseline: 1.2846x; 1.2846x over previous
#include <cuda_runtime.h>
#include <cstdint>

// ---------------- problem constants ----------------
#define BB   2048      // batch
#define LL   64        // words / sentence
#define DD   300       // embedding dim (K of encoder GEMM)
#define CC   512       // conv out channels
#define HH   2048      // fc hidden
// encoder GEMM: M = BB*LL = 131072, N = CC = 512, K = 300
// fc1 GEMM:     M = BB = 2048,     N = HH = 2048, K = 2*CC = 1024

// ---------------- scratch (no allocations allowed) ----------------
__device__ float g_e[2 * BB * CC];      // e1 | e2   (8 MB)
__device__ float g_h[(size_t)BB * HH];  // tanh hidden (16 MB)

// ---------------- helpers ----------------
__device__ __forceinline__ uint32_t f2tf(float f) {
    uint32_t r;
    asm("cvt.rna.tf32.f32 %0, %1;" : "=r"(r) : "f"(f));
    return r;
}

__device__ __forceinline__ void mma_tf32(float c[4], const uint32_t a[4], const uint32_t b[2]) {
    asm volatile(
        "mma.sync.aligned.m16n8k8.row.col.f32.tf32.tf32.f32 "
        "{%0,%1,%2,%3}, {%4,%5,%6,%7}, {%8,%9}, {%0,%1,%2,%3};"
        : "+f"(c[0]), "+f"(c[1]), "+f"(c[2]), "+f"(c[3])
        : "r"(a[0]), "r"(a[1]), "r"(a[2]), "r"(a[3]), "r"(b[0]), "r"(b[1]));
}

__device__ __forceinline__ void cpa16(uint32_t dst, const void* src, int sz) {
    asm volatile("cp.async.cg.shared.global [%0], [%1], 16, %2;"
                 :: "r"(dst), "l"(src), "r"(sz));
}
__device__ __forceinline__ void cpa_commit() {
    asm volatile("cp.async.commit_group;");
}

// ---------------- tiling ----------------
// CTA tile: 256 (M) x 128 (N), K-tile 32, 8 warps each owning a 64x64 subtile.
#define KT    32
#define PADW  36                       // smem row stride (words)
#define AW    (256 * PADW)             // words per A stage
#define BWW   (128 * PADW)             // words per B stage
#define SMEM_WORDS (2 * (AW + BWW))
#define SMEM_BYTES (SMEM_WORDS * 4)    // 110592

// ---------------- fragment load (raw fp32 smem -> tf32 regs) ----------------
__device__ __forceinline__ void load_frag(const uint32_t* __restrict__ As,
                                          const uint32_t* __restrict__ Bs,
                                          int kk, int wm, int wn, int g, int tg,
                                          uint32_t a[4][4], uint32_t b[8][2])
{
    #pragma unroll
    for (int f = 0; f < 4; f++) {
        int r = wm * 64 + f * 16;
        a[f][0] = f2tf(__uint_as_float(As[(r + g    ) * PADW + kk + tg    ]));
        a[f][1] = f2tf(__uint_as_float(As[(r + g + 8) * PADW + kk + tg    ]));
        a[f][2] = f2tf(__uint_as_float(As[(r + g    ) * PADW + kk + tg + 4]));
        a[f][3] = f2tf(__uint_as_float(As[(r + g + 8) * PADW + kk + tg + 4]));
    }
    #pragma unroll
    for (int ni = 0; ni < 8; ni++) {
        int c = wn * 64 + ni * 8;
        b[ni][0] = f2tf(__uint_as_float(Bs[(c + g) * PADW + kk + tg    ]));
        b[ni][1] = f2tf(__uint_as_float(Bs[(c + g) * PADW + kk + tg + 4]));
    }
}

__device__ __forceinline__ void mma_frag(const uint32_t a[4][4], const uint32_t b[8][2],
                                         float acc[4][8][4])
{
    #pragma unroll
    for (int f = 0; f < 4; f++)
        #pragma unroll
        for (int ni = 0; ni < 8; ni++)
            mma_tf32(acc[f][ni], a[f], b[ni]);
}

// software-pipelined compute on one staged K-tile (NKS k-steps of 8)
template <int NKS>
__device__ __forceinline__ void compute_tile_pipe(const uint32_t* __restrict__ As,
                                                  const uint32_t* __restrict__ Bs,
                                                  int wm, int wn, int g, int tg,
                                                  float acc[4][8][4])
{
    uint32_t a[2][4][4], b[2][8][2];
    load_frag(As, Bs, 0, wm, wn, g, tg, a[0], b[0]);
    #pragma unroll
    for (int kk = 0; kk < NKS; kk++) {
        if (kk + 1 < NKS)
            load_frag(As, Bs, (kk + 1) * 8, wm, wn, g, tg,
                      a[(kk + 1) & 1], b[(kk + 1) & 1]);
        mma_frag(a[kk & 1], b[kk & 1], acc);
    }
}

// =====================================================================
// Kernel 1: encoder.  grid = (C/128, (B*L)/256, 2), block = 256
// relu(max_L(x @ Wc^T) + bc) folded into epilogue; warp m-strip = 1 sentence.
// cp.async double-buffered staging (raw fp32) + in-register fragment pipeline.
// =====================================================================
__global__ __launch_bounds__(256, 1)
void encode_kernel(const float* __restrict__ x1, const float* __restrict__ x2,
                   const float* __restrict__ Wc, const float* __restrict__ bc)
{
    extern __shared__ uint32_t sh[];
    uint32_t sbase = (uint32_t)__cvta_generic_to_shared(sh);

    const float* __restrict__ x = (blockIdx.z == 0) ? x1 : x2;
    const int mbase = blockIdx.y * 256;
    const int nbase = blockIdx.x * 128;

    const int tid  = threadIdx.x;
    const int warp = tid >> 5, lane = tid & 31;
    const int wm = warp >> 1;      // 4 m-strips of 64 rows (one sentence each)
    const int wn = warp & 1;       // 2 n-strips of 64 cols
    const int g  = lane >> 2, tg = lane & 3;

    const int lrow = tid >> 3;     // loader row base
    const int kch  = (tid & 7) * 4;

    auto cpA = [&](int buf, int kb) {
        #pragma unroll
        for (int it = 0; it < 8; it++) {
            int row = lrow + it * 32;
            int k   = kb + kch;
            const float* src = x + (size_t)(mbase + row) * DD + k;
            uint32_t dst = sbase + (uint32_t)(buf * AW + row * PADW + kch) * 4u;
            cpa16(dst, src, (k < DD) ? 16 : 0);
        }
    };
    auto cpB = [&](int buf, int kb) {
        #pragma unroll
        for (int it = 0; it < 4; it++) {
            int row = lrow + it * 32;
            int k   = kb + kch;
            const float* src = Wc + (size_t)(nbase + row) * DD + k;
            uint32_t dst = sbase + (uint32_t)(2 * AW + buf * BWW + row * PADW + kch) * 4u;
            cpa16(dst, src, (k < DD) ? 16 : 0);
        }
    };

    float acc[4][8][4] = {};

    const int NK = 10;     // K tiles of 32 (300 -> 320 padded; last tile trimmed)
    cpA(0, 0);
    cpB(0, 0);
    cpa_commit();

    #pragma unroll 1
    for (int i = 0; i < NK; i++) {
        if (i + 1 < NK) {
            cpA((i + 1) & 1, (i + 1) * KT);
            cpB((i + 1) & 1, (i + 1) * KT);
            cpa_commit();
            asm volatile("cp.async.wait_group 1;");
        } else {
            asm volatile("cp.async.wait_group 0;");
        }
        __syncthreads();

        const uint32_t* As = sh + (i & 1) * AW;
        const uint32_t* Bs = sh + 2 * AW + (i & 1) * BWW;
        if (i == NK - 1)   // k = 288..303 covers the 300 real columns
            compute_tile_pipe<2>(As, Bs, wm, wn, g, tg, acc);
        else
            compute_tile_pipe<4>(As, Bs, wm, wn, g, tg, acc);
        __syncthreads();   // buffer reuse guard
    }

    // ---- epilogue: max over the warp's 64 rows (== one sentence) ----
    // relu(max + bc) == max(relu(.+bc)) since bias is per-column.
    const size_t sent = (size_t)blockIdx.y * 4 + wm;       // global sentence
    float* __restrict__ eout = g_e + ((size_t)blockIdx.z * BB + sent) * CC + nbase;

    #pragma unroll
    for (int ni = 0; ni < 8; ni++) {
        #pragma unroll
        for (int j = 0; j < 2; j++) {
            float m = -3.4e38f;
            #pragma unroll
            for (int f = 0; f < 4; f++)
                m = fmaxf(m, fmaxf(acc[f][ni][j], acc[f][ni][j + 2]));
            #pragma unroll
            for (int off = 4; off < 32; off <<= 1)
                m = fmaxf(m, __shfl_xor_sync(0xffffffffu, m, off));
            if (g == 0) {
                int col = wn * 64 + ni * 8 + 2 * tg + j;
                eout[col] = fmaxf(m + bc[nbase + col], 0.f);
            }
        }
    }
}

// =====================================================================
// Kernel 2: FC1.  grid = (H/128, B/256), block = 256
// feat = [e1-e2 | e1*e2] computed on the fly in the A-tile prefetch (regs).
// h = tanh(feat @ W1^T + b1)
// =====================================================================
__device__ __forceinline__ void sts_A(uint32_t* __restrict__ sh, int buf,
                                      const float4* __restrict__ ra, int tid)
{
    #pragma unroll
    for (int it = 0; it < 8; it++) {
        int id  = tid + it * 256;
        int row = id >> 3, ch = id & 7;
        uint32_t* d = sh + buf * AW + row * PADW + ch * 4;
        d[0] = __float_as_uint(ra[it].x); d[1] = __float_as_uint(ra[it].y);
        d[2] = __float_as_uint(ra[it].z); d[3] = __float_as_uint(ra[it].w);
    }
}
__device__ __forceinline__ void sts_B(uint32_t* __restrict__ sh, int buf,
                                      const float4* __restrict__ rb, int tid)
{
    #pragma unroll
    for (int it = 0; it < 4; it++) {
        int id  = tid + it * 256;
        int row = id >> 3, ch = id & 7;
        uint32_t* d = sh + 2 * AW + buf * BWW + row * PADW + ch * 4;
        d[0] = __float_as_uint(rb[it].x); d[1] = __float_as_uint(rb[it].y);
        d[2] = __float_as_uint(rb[it].z); d[3] = __float_as_uint(rb[it].w);
    }
}

__global__ __launch_bounds__(256, 1)
void fc1_kernel(const float* __restrict__ W1, const float* __restrict__ b1)
{
    extern __shared__ uint32_t sh[];

    const int mbase = blockIdx.y * 256;
    const int nbase = blockIdx.x * 128;

    const int tid  = threadIdx.x;
    const int warp = tid >> 5, lane = tid & 31;
    const int wm = warp >> 1, wn = warp & 1;
    const int g  = lane >> 2, tg = lane & 3;

    const float* __restrict__ e1 = g_e;
    const float* __restrict__ e2 = g_e + (size_t)BB * CC;

    const int arow = mbase + (tid >> 3);
    const int brow = nbase + (tid >> 3);
    const int kch  = (tid & 7) * 4;

    float acc[4][8][4] = {};
    float4 ra[8], rb[4];

    auto load_feat = [&](int it, int j) -> float4 {
        int r = arow + it * 32;
        if (j < CC) {
            float4 p = *(const float4*)(e1 + (size_t)r * CC + j);
            float4 q = *(const float4*)(e2 + (size_t)r * CC + j);
            return make_float4(p.x - q.x, p.y - q.y, p.z - q.z, p.w - q.w);
        } else {
            int j2 = j - CC;
            float4 p = *(const float4*)(e1 + (size_t)r * CC + j2);
            float4 q = *(const float4*)(e2 + (size_t)r * CC + j2);
            return make_float4(p.x * q.x, p.y * q.y, p.z * q.z, p.w * q.w);
        }
    };

    // ---- prologue: tile 0 ----
    {
        #pragma unroll
        for (int it = 0; it < 8; it++) ra[it] = load_feat(it, kch);
        #pragma unroll
        for (int it = 0; it < 4; it++)
            rb[it] = *(const float4*)(W1 + (size_t)(brow + it * 32) * (2 * CC) + kch);
        sts_A(sh, 0, ra, tid);
        sts_B(sh, 0, rb, tid);
        __syncthreads();
    }

    const int NK = (2 * CC) / KT;   // 32
    #pragma unroll 1
    for (int i = 0; i < NK - 1; i++) {
        const int kb = (i + 1) * KT;
        #pragma unroll
        for (int it = 0; it < 8; it++) ra[it] = load_feat(it, kb + kch);
        #pragma unroll
        for (int it = 0; it < 4; it++)
            rb[it] = *(const float4*)(W1 + (size_t)(brow + it * 32) * (2 * CC) + kb + kch);

        {
            const uint32_t* As = sh + (i & 1) * AW;
            const uint32_t* Bs = sh + 2 * AW + (i & 1) * BWW;
            compute_tile_pipe<4>(As, Bs, wm, wn, g, tg, acc);
        }

        sts_A(sh, (i + 1) & 1, ra, tid);
        sts_B(sh, (i + 1) & 1, rb, tid);
        __syncthreads();
    }
    {
        const uint32_t* As = sh + ((NK - 1) & 1) * AW;
        const uint32_t* Bs = sh + 2 * AW + ((NK - 1) & 1) * BWW;
        compute_tile_pipe<4>(As, Bs, wm, wn, g, tg, acc);
    }

    // epilogue: bias + tanh, direct store
    #pragma unroll
    for (int f = 0; f < 4; f++) {
        #pragma unroll
        for (int ni = 0; ni < 8; ni++) {
            #pragma unroll
            for (int q = 0; q < 4; q++) {
                int row = mbase + wm * 64 + f * 16 + g + ((q >> 1) ? 8 : 0);
                int col = nbase + wn * 64 + ni * 8 + 2 * tg + (q & 1);
                g_h[(size_t)row * HH + col] = tanhf(acc[f][ni][q] + b1[col]);
            }
        }
    }
}

// =====================================================================
// Kernel 3: FC2 (H -> 1), fp32, float4 loads.  grid = B, block = 256
// =====================================================================
__global__ __launch_bounds__(256)
void fc2_kernel(const float* __restrict__ W2, const float* __restrict__ b2,
                float* __restrict__ out)
{
    const int b = blockIdx.x;
    const float4* __restrict__ h4 = (const float4*)(g_h + (size_t)b * HH);
    const float4* __restrict__ w4 = (const float4*)W2;
    float s = 0.f;
    #pragma unroll
    for (int i = 0; i < 2; i++) {
        int idx = threadIdx.x + i * 256;
        float4 hv = h4[idx], wv = w4[idx];
        s += hv.x * wv.x + hv.y * wv.y + hv.z * wv.z + hv.w * wv.w;
    }
    #pragma unroll
    for (int off = 16; off > 0; off >>= 1)
        s += __shfl_xor_sync(0xffffffffu, s, off);
    __shared__ float sm[8];
    int warp = threadIdx.x >> 5, lane = threadIdx.x & 31;
    if (lane == 0) sm[warp] = s;
    __syncthreads();
    if (warp == 0) {
        float v = (lane < 8) ? sm[lane] : 0.f;
        #pragma unroll
        for (int off = 4; off > 0; off >>= 1)
            v += __shfl_xor_sync(0xffffffffu, v, off);
        if (lane == 0) out[b] = v + b2[0];
    }
}

// =====================================================================
extern "C" void kernel_launch(void* const* d_in, const int* in_sizes, int n_in,
                              void* d_out, int out_size)
{
    (void)in_sizes; (void)n_in; (void)out_size;
    const float* x1 = (const float*)d_in[0];
    const float* x2 = (const float*)d_in[1];
    const float* Wc = (const float*)d_in[2];
    const float* bc = (const float*)d_in[3];
    const float* W1 = (const float*)d_in[4];
    const float* b1 = (const float*)d_in[5];
    const float* W2 = (const float*)d_in[6];
    const float* b2 = (const float*)d_in[7];
    float* out = (float*)d_out;

    static bool attr_done = false;
    if (!attr_done) {
        cudaFuncSetAttribute(encode_kernel,
                             cudaFuncAttributeMaxDynamicSharedMemorySize, SMEM_BYTES);
        cudaFuncSetAttribute(fc1_kernel,
                             cudaFuncAttributeMaxDynamicSharedMemorySize, SMEM_BYTES);
        attr_done = true;
    }

    dim3 g1(CC / 128, (BB * LL) / 256, 2);        // 4 x 512 x 2 = 4096 CTAs
    encode_kernel<<<g1, 256, SMEM_BYTES>>>(x1, x2, Wc, bc);

    dim3 g2(HH / 128, BB / 256);                  // 16 x 8 = 128 CTAs
    fc1_kernel<<<g2, 256, SMEM_BYTES>>>(W1, b1);

    fc2_kernel<<<BB, 256>>>(W2, b2, out);
}